// round 14
// baseline (speedup 1.0000x reference)
#include <cuda_runtime.h>
#include <cuda_bf16.h>
#include <cstdint>

// SIR SDE: 8192 trajectories x 4900 effective steps, sampled every 100 steps (49 samples),
// features: max, (argmax+u)/49, std(diff(log x)).
//
// R14 = R13 (116.4us: CH=40, NBUF=5/AHEAD=4 cp.async pipeline, 128 blocks x 64 thr,
// q = rec*s, z = i/DT) + ONE delta: the two 20-step half-bursts are merged into one
// 40-step burst (dwv[40], single LDS burst, single unrolled compute run). Removes the
// mid-chunk LDS-burst stall + loop seam (~60-80 cyc x 122 chunks). Samples are predicated
// inline at k==19 (chunks c%5==2) and k==39 (c%5==4); k is a compile-time constant under
// full unroll so these are two chunk-level predicates. Registers ~120 are fine at 1
// block/SM (occupancy is irrelevant; chain-latency-bound).

#define BSZ    8192
#define CH     40            // steps per chunk
#define NCHUNK 123           // covers steps 0..4919 (last sample at step 4899)
#define NBUF   5             // smem buffers per warp
#define AHEAD  4             // chunks in flight
#define WPB    2             // warps per block
#define THREADS (WPB * 32)

__device__ __forceinline__ void cp_async16(uint32_t saddr, const void* gptr) {
    asm volatile("cp.async.ca.shared.global [%0], [%1], 16;" :: "r"(saddr), "l"(gptr));
}
__device__ __forceinline__ void cp_commit() {
    asm volatile("cp.async.commit_group;");
}
template <int N>
__device__ __forceinline__ void cp_wait() {
    asm volatile("cp.async.wait_group %0;" :: "n"(N));
}
__device__ __forceinline__ float sqrt_approx(float x) {
    float r;
    asm("sqrt.approx.f32 %0, %1;" : "=f"(r) : "f"(x));
    return r;
}

__global__ __launch_bounds__(THREADS, 1)
void sir_sde_kernel(const float* __restrict__ cond,
                    const float* __restrict__ dW,
                    const float* __restrict__ u,
                    float* __restrict__ out)
{
    __shared__ float sdw[WPB][NBUF * CH * 32];   // per-warp: 5 bufs x 40 steps x 32 lanes

    const int lane = threadIdx.x & 31;
    const int w    = threadIdx.x >> 5;
    const int b0   = blockIdx.x * THREADS + w * 32;   // first trajectory of this warp
    const int b    = b0 + lane;

    // ---------- per-trajectory parameters ----------
    const float inf_rate = cond[b * 4 + 0];
    const float rec      = cond[b * 4 + 1];
    const float mr       = cond[b * 4 + 2];
    const float vol      = cond[b * 4 + 3];

    const float DT      = 0.01f;
    const float r0_init = __fdiv_rn(inf_rate, rec);
    const float sdt     = sqrtf(DT);
    const float dtmr    = DT * mr;
    const float om      = 1.0f - dtmr;        // r0' = om*r0 + c1 + sqrt(|r0|)*c2
    const float c1      = dtmr * r0_init;
    const float kvol    = vol * sdt;
    const float ndtrec  = -DT * rec;          // q' = q + ndtrec*ni
    const float omr     = 1.0f + ndtrec;      // z' = omr*z + ni   (z = i/DT)

    // ---------- state (s -> q = rec*s, i -> z = i/DT) ----------
    float q  = rec * 0.99f;
    float z  = 1.0f;                          // i0 = 0.01 = DT*1
    float r0 = r0_init;

    // ---------- feature accumulators ----------
    float cur_max = -3.402823466e38f;
    int   cur_arg = 0;
    int   js      = 0;                        // running sample index (0..48)
    float prev_lg = 0.0f;
    float sumd = 0.0f, sumd2 = 0.0f;

    // ---------- cp.async chunk copier (per warp, self-contained) ----------
    uint32_t smem_base;
    asm("{ .reg .u64 t; cvta.to.shared.u64 t, %1; cvt.u32.u64 %0, t; }"
        : "=r"(smem_base) : "l"(&sdw[w][0]));

    const char* gbase = (const char*)(dW + b0);

    // chunk = 40 rows x 128 B = 5120 B; thread copies 10 x 16 B.
    auto issue_chunk = [&](int c, int bufidx) {
        const char* g = gbase + (size_t)c * CH * BSZ * 4;
        uint32_t sb = smem_base + bufidx * (CH * 128);
#pragma unroll
        for (int i = 0; i < 10; ++i) {
            int f   = i * 512 + lane * 16;      // flat byte offset in this warp's buffer
            int row = f >> 7;                   // /128
            int col = f & 127;
            cp_async16(sb + f, g + (size_t)row * BSZ * 4 + col);
        }
        cp_commit();
    };

    auto take_sample = [&](void) {
        float x = DT * z;                       // i = DT*z
        if ((__float_as_uint(x) & 0x7f800000u) == 0x7f800000u) x = 0.0f; // nan/inf -> 0
        x = fmaxf(x, 1e-5f);
        if (x > cur_max) { cur_max = x; cur_arg = js; }
        const float lg = logf(x);
        if (js > 0) {
            const float d = lg - prev_lg;
            sumd  += d;
            sumd2 += d * d;
        }
        prev_lg = lg;
        ++js;
    };

    // prologue: chunks 0..AHEAD-1 in flight
#pragma unroll
    for (int p = 0; p < AHEAD; ++p) issue_chunk(p, p);

    const float* sbuf = &sdw[w][0];

#pragma unroll 1
    for (int c = 0; c < NCHUNK; ++c) {
        // Steady state: pending groups {c..c+AHEAD-1} -> wait<AHEAD-1> drains chunk c.
        // Tail (no new issues): pending count < AHEAD -> full drain.
        if (c + AHEAD >= NCHUNK) cp_wait<0>();
        else                     cp_wait<AHEAD - 1>();
        __syncwarp();

        // single 40-float burst copy of chunk c (conflict-free LDS)
        float dwv[CH];
        const float* sp = sbuf + (c % NBUF) * (CH * 32) + lane;
#pragma unroll
        for (int k = 0; k < CH; ++k) dwv[k] = sp[k * 32];

        // refill chunk c+AHEAD into buffer (c+AHEAD)%NBUF
        // (NBUF = AHEAD+1: that buffer's consumer was chunk c-1 -> done)
        if (c + AHEAD < NCHUNK) issue_chunk(c + AHEAD, (c + AHEAD) % NBUF);

        const bool s19 = (c % 5) == 2;          // sample after step c*40+19
        const bool s39 = (c % 5) == 4;          // sample after step c*40+39

        // ---------- 40 Euler-Maruyama steps (fully unrolled, inline samples) ----------
#pragma unroll
        for (int k = 0; k < CH; ++k) {
            const float c2 = dwv[k] * kvol;     // off the critical chain
            const float ni = r0 * q;            // newly_infected (= r0*rec*s)
            const float sq = sqrt_approx(fabsf(r0));
            const float t  = fmaf(r0, om, c1);
            r0 = fmaf(sq, c2, t);               // chain: MUFU + FFMA
            q  = fmaf(ni, ndtrec, q);
            z  = fmaf(omr, z, ni);              // i-update in one FFMA (z = i/DT)

            if (k == 19 && s19) take_sample();
            if (k == 39 && s39) take_sample();
        }
    }

    // ---------- features ----------
    const float max_at = ((float)cur_arg + u[b]) / 49.0f;
    const float mean   = sumd * (1.0f / 48.0f);
    float var = sumd2 * (1.0f / 48.0f) - mean * mean;   // ddof=0
    var = fmaxf(var, 0.0f);

    out[b * 3 + 0] = cur_max;
    out[b * 3 + 1] = max_at;
    out[b * 3 + 2] = sqrtf(var);
}

extern "C" void kernel_launch(void* const* d_in, const int* in_sizes, int n_in,
                              void* d_out, int out_size)
{
    const float* cond = (const float*)d_in[0];   // (8192, 4)
    const float* dW   = (const float*)d_in[1];   // (5000, 8192)
    const float* u    = (const float*)d_in[2];   // (8192,)
    float* out        = (float*)d_out;           // (8192, 3)

    sir_sde_kernel<<<BSZ / THREADS, THREADS>>>(cond, dW, u, out);
}

// round 15
// speedup vs baseline: 1.1709x; 1.1709x over previous
#include <cuda_runtime.h>
#include <cuda_bf16.h>
#include <cstdint>

// SIR SDE: 8192 trajectories x 4900 steps, sampled every 100 steps (49 samples),
// features: max, (argmax+u)/49, std(diff(log x)).
//
// R15 = R13's proven inner sub-unit (20-step {LDS burst -> compute} blocks; R14 proved
// merging bursts hurts) with CH extended 40 -> 100 (NCHUNK=49) to amortize the ~150-cyc
// per-chunk overhead (wait_group, syncwarp, refill, branch) over 2.5x more steps.
// Sampling now falls exactly at each chunk end (step c*100+99) -> no predicates, js = c.
// 49 x 100 = 4900 exactly: no overrun. Pipeline NBUF=3/AHEAD=2 (25.6KB/warp in flight),
// full drain for the final AHEAD chunks. 128 blocks x 64 threads unchanged.

#define BSZ    8192
#define CH     100           // steps per chunk = sample period
#define HS     20            // sub-burst steps (R13's proven unit)
#define NCHUNK 49
#define NBUF   3             // smem buffers per warp
#define AHEAD  2             // chunks in flight
#define WPB    2             // warps per block
#define THREADS (WPB * 32)

__device__ __forceinline__ void cp_async16(uint32_t saddr, const void* gptr) {
    asm volatile("cp.async.ca.shared.global [%0], [%1], 16;" :: "r"(saddr), "l"(gptr));
}
__device__ __forceinline__ void cp_commit() {
    asm volatile("cp.async.commit_group;");
}
template <int N>
__device__ __forceinline__ void cp_wait() {
    asm volatile("cp.async.wait_group %0;" :: "n"(N));
}
__device__ __forceinline__ float sqrt_approx(float x) {
    float r;
    asm("sqrt.approx.f32 %0, %1;" : "=f"(r) : "f"(x));
    return r;
}

__global__ __launch_bounds__(THREADS, 1)
void sir_sde_kernel(const float* __restrict__ cond,
                    const float* __restrict__ dW,
                    const float* __restrict__ u,
                    float* __restrict__ out)
{
    __shared__ float sdw[WPB][NBUF * CH * 32];   // per-warp: 3 bufs x 100 steps x 32 lanes

    const int lane = threadIdx.x & 31;
    const int w    = threadIdx.x >> 5;
    const int b0   = blockIdx.x * THREADS + w * 32;   // first trajectory of this warp
    const int b    = b0 + lane;

    // ---------- per-trajectory parameters ----------
    const float inf_rate = cond[b * 4 + 0];
    const float rec      = cond[b * 4 + 1];
    const float mr       = cond[b * 4 + 2];
    const float vol      = cond[b * 4 + 3];

    const float DT      = 0.01f;
    const float r0_init = __fdiv_rn(inf_rate, rec);
    const float sdt     = sqrtf(DT);
    const float dtmr    = DT * mr;
    const float om      = 1.0f - dtmr;        // r0' = om*r0 + c1 + sqrt(|r0|)*c2
    const float c1      = dtmr * r0_init;
    const float kvol    = vol * sdt;
    const float ndtrec  = -DT * rec;          // q' = q + ndtrec*ni
    const float omr     = 1.0f + ndtrec;      // z' = omr*z + ni   (z = i/DT)

    // ---------- state (s -> q = rec*s, i -> z = i/DT) ----------
    float q  = rec * 0.99f;
    float z  = 1.0f;                          // i0 = 0.01 = DT*1
    float r0 = r0_init;

    // ---------- feature accumulators ----------
    float cur_max = -3.402823466e38f;
    int   cur_arg = 0;
    float prev_lg = 0.0f;
    float sumd = 0.0f, sumd2 = 0.0f;

    // ---------- cp.async chunk copier (per warp, self-contained) ----------
    uint32_t smem_base;
    asm("{ .reg .u64 t; cvta.to.shared.u64 t, %1; cvt.u32.u64 %0, t; }"
        : "=r"(smem_base) : "l"(&sdw[w][0]));

    const char* gbase = (const char*)(dW + b0);

    // chunk = 100 rows x 128 B = 12800 B; thread copies 25 x 16 B.
    auto issue_chunk = [&](int c, int bufidx) {
        const char* g = gbase + (size_t)c * CH * BSZ * 4;
        uint32_t sb = smem_base + bufidx * (CH * 128);
#pragma unroll
        for (int i = 0; i < 25; ++i) {
            int f   = i * 512 + lane * 16;      // flat byte offset in this warp's buffer
            int row = f >> 7;                   // /128
            int col = f & 127;
            cp_async16(sb + f, g + (size_t)row * BSZ * 4 + col);
        }
        cp_commit();
    };

    // one 20-step sub-burst: LDS 20 noise values, run 20 Euler-Maruyama steps
    float dwv[HS];
    auto run_sub = [&](const float* sp, int h) {
#pragma unroll
        for (int k = 0; k < HS; ++k) dwv[k] = sp[(h * HS + k) * 32];
#pragma unroll
        for (int k = 0; k < HS; ++k) {
            const float c2 = dwv[k] * kvol;     // off the critical chain
            const float ni = r0 * q;            // newly_infected (= r0*rec*s)
            const float sq = sqrt_approx(fabsf(r0));
            const float t  = fmaf(r0, om, c1);
            r0 = fmaf(sq, c2, t);               // chain: MUFU + FFMA
            q  = fmaf(ni, ndtrec, q);
            z  = fmaf(omr, z, ni);              // i-update in one FFMA (z = i/DT)
        }
    };

    // prologue: chunks 0..AHEAD-1 in flight
#pragma unroll
    for (int p = 0; p < AHEAD; ++p) issue_chunk(p, p);

    const float* sbuf = &sdw[w][0];

#pragma unroll 1
    for (int c = 0; c < NCHUNK; ++c) {
        // Steady state: pending groups {c, c+1} -> wait<1> drains chunk c.
        // Tail (no new issues): pending count < AHEAD -> full drain.
        if (c + AHEAD >= NCHUNK) cp_wait<0>();
        else                     cp_wait<AHEAD - 1>();
        __syncwarp();

        const float* sp = sbuf + (c % NBUF) * (CH * 32) + lane;

        // sub-burst 0, then refill (its buffer's last consumer was chunk c-1 -> done)
        run_sub(sp, 0);
        if (c + AHEAD < NCHUNK) issue_chunk(c + AHEAD, (c + AHEAD) % NBUF);

        run_sub(sp, 1);
        run_sub(sp, 2);
        run_sub(sp, 3);
        run_sub(sp, 4);

        // ---------- sample at step c*100+99 ----------
        float x = DT * z;                       // i = DT*z
        if ((__float_as_uint(x) & 0x7f800000u) == 0x7f800000u) x = 0.0f; // nan/inf -> 0
        x = fmaxf(x, 1e-5f);
        if (x > cur_max) { cur_max = x; cur_arg = c; }
        const float lg = logf(x);
        if (c > 0) {
            const float d = lg - prev_lg;
            sumd  += d;
            sumd2 += d * d;
        }
        prev_lg = lg;
    }

    // ---------- features ----------
    const float max_at = ((float)cur_arg + u[b]) / 49.0f;
    const float mean   = sumd * (1.0f / 48.0f);
    float var = sumd2 * (1.0f / 48.0f) - mean * mean;   // ddof=0
    var = fmaxf(var, 0.0f);

    out[b * 3 + 0] = cur_max;
    out[b * 3 + 1] = max_at;
    out[b * 3 + 2] = sqrtf(var);
}

extern "C" void kernel_launch(void* const* d_in, const int* in_sizes, int n_in,
                              void* d_out, int out_size)
{
    const float* cond = (const float*)d_in[0];   // (8192, 4)
    const float* dW   = (const float*)d_in[1];   // (5000, 8192)
    const float* u    = (const float*)d_in[2];   // (8192,)
    float* out        = (float*)d_out;           // (8192, 3)

    sir_sde_kernel<<<BSZ / THREADS, THREADS>>>(cond, dW, u, out);
}

// round 16
// speedup vs baseline: 1.2224x; 1.0440x over previous
#include <cuda_runtime.h>
#include <cuda_bf16.h>
#include <cstdint>

// SIR SDE: 8192 trajectories x 4900 steps, sampled every 100 steps (49 samples),
// features: max, (argmax+u)/49, std(diff(log x)).
//
// R16 = R15 (105.6us: CH=100, NBUF=3/AHEAD=2, 20-step sub-bursts, sample at chunk end)
// + two seam removals:
//  1) refill cp.asyncs spread 5x5 across the sub-bursts (single commit per chunk; the
//     ~200-cyc LDGSTS issue lump now hides in per-step issue slack),
//  2) uniform refill with chunk index clamped to the last chunk -> pending-group count
//     is ALWAYS 2, wait<1> is always correct, no tail branch / cp_wait<0> in the loop.
//     Clamped groups land in buffers with no future consumers (checked: buf1@c=47,
//     buf2@c=48). One cp_wait<0> after the loop drains before exit.

#define BSZ    8192
#define CH     100           // steps per chunk = sample period
#define HS     20            // sub-burst steps (proven unit)
#define NCHUNK 49
#define NBUF   3             // smem buffers per warp
#define AHEAD  2             // chunks in flight
#define WPB    2             // warps per block
#define THREADS (WPB * 32)

__device__ __forceinline__ void cp_async16(uint32_t saddr, const void* gptr) {
    asm volatile("cp.async.ca.shared.global [%0], [%1], 16;" :: "r"(saddr), "l"(gptr));
}
__device__ __forceinline__ void cp_commit() {
    asm volatile("cp.async.commit_group;");
}
template <int N>
__device__ __forceinline__ void cp_wait() {
    asm volatile("cp.async.wait_group %0;" :: "n"(N));
}
__device__ __forceinline__ float sqrt_approx(float x) {
    float r;
    asm("sqrt.approx.f32 %0, %1;" : "=f"(r) : "f"(x));
    return r;
}

__global__ __launch_bounds__(THREADS, 1)
void sir_sde_kernel(const float* __restrict__ cond,
                    const float* __restrict__ dW,
                    const float* __restrict__ u,
                    float* __restrict__ out)
{
    __shared__ float sdw[WPB][NBUF * CH * 32];   // per-warp: 3 bufs x 100 steps x 32 lanes

    const int lane = threadIdx.x & 31;
    const int w    = threadIdx.x >> 5;
    const int b0   = blockIdx.x * THREADS + w * 32;   // first trajectory of this warp
    const int b    = b0 + lane;

    // ---------- per-trajectory parameters ----------
    const float inf_rate = cond[b * 4 + 0];
    const float rec      = cond[b * 4 + 1];
    const float mr       = cond[b * 4 + 2];
    const float vol      = cond[b * 4 + 3];

    const float DT      = 0.01f;
    const float r0_init = __fdiv_rn(inf_rate, rec);
    const float sdt     = sqrtf(DT);
    const float dtmr    = DT * mr;
    const float om      = 1.0f - dtmr;        // r0' = om*r0 + c1 + sqrt(|r0|)*c2
    const float c1      = dtmr * r0_init;
    const float kvol    = vol * sdt;
    const float ndtrec  = -DT * rec;          // q' = q + ndtrec*ni
    const float omr     = 1.0f + ndtrec;      // z' = omr*z + ni   (z = i/DT)

    // ---------- state (s -> q = rec*s, i -> z = i/DT) ----------
    float q  = rec * 0.99f;
    float z  = 1.0f;                          // i0 = 0.01 = DT*1
    float r0 = r0_init;

    // ---------- feature accumulators ----------
    float cur_max = -3.402823466e38f;
    int   cur_arg = 0;
    float prev_lg = 0.0f;
    float sumd = 0.0f, sumd2 = 0.0f;

    // ---------- cp.async machinery (per warp, self-contained) ----------
    uint32_t smem_base;
    asm("{ .reg .u64 t; cvta.to.shared.u64 t, %1; cvt.u32.u64 %0, t; }"
        : "=r"(smem_base) : "l"(&sdw[w][0]));

    const char* gbase = (const char*)(dW + b0);

    // one refill batch: 5 cp.asyncs = 2560 B = rows [h*20, h*20+20) of chunk c
    auto issue_batch = [&](int c, int bufidx, int h) {
        const char* g = gbase + (size_t)c * CH * BSZ * 4;
        uint32_t sb = smem_base + bufidx * (CH * 128);
#pragma unroll
        for (int i = 0; i < 5; ++i) {
            int f   = (h * 5 + i) * 512 + lane * 16;   // flat byte offset in buffer
            int row = f >> 7;                          // /128
            int col = f & 127;
            cp_async16(sb + f, g + (size_t)row * BSZ * 4 + col);
        }
    };

    // one 20-step sub-burst: LDS 20 noise values, run 20 Euler-Maruyama steps
    float dwv[HS];
    auto run_sub = [&](const float* sp, int h) {
#pragma unroll
        for (int k = 0; k < HS; ++k) dwv[k] = sp[(h * HS + k) * 32];
#pragma unroll
        for (int k = 0; k < HS; ++k) {
            const float c2 = dwv[k] * kvol;     // off the critical chain
            const float ni = r0 * q;            // newly_infected (= r0*rec*s)
            const float sq = sqrt_approx(fabsf(r0));
            const float t  = fmaf(r0, om, c1);
            r0 = fmaf(sq, c2, t);               // chain: MUFU + FFMA
            q  = fmaf(ni, ndtrec, q);
            z  = fmaf(omr, z, ni);              // i-update in one FFMA (z = i/DT)
        }
    };

    // prologue: chunks 0,1 fully in flight (one group each)
#pragma unroll
    for (int p = 0; p < AHEAD; ++p) {
#pragma unroll
        for (int h = 0; h < 5; ++h) issue_batch(p, p, h);
        cp_commit();
    }

    const float* sbuf = &sdw[w][0];

#pragma unroll 1
    for (int c = 0; c < NCHUNK; ++c) {
        // Invariant: exactly 2 groups pending here ({c, c+1}); wait<1> drains chunk c.
        cp_wait<AHEAD - 1>();
        __syncwarp();

        const float* sp = sbuf + (c % NBUF) * (CH * 32) + lane;

        // refill target: always issue one full group; chunk index clamped at the end
        // (clamped groups fill buffers that are never read again -> harmless, keeps
        // the pending-group invariant so no tail special case is needed).
        const int cnext  = (c + AHEAD < NCHUNK) ? (c + AHEAD) : (NCHUNK - 1);
        const int bufidx = (c + AHEAD) % NBUF;

        run_sub(sp, 0); issue_batch(cnext, bufidx, 0);
        run_sub(sp, 1); issue_batch(cnext, bufidx, 1);
        run_sub(sp, 2); issue_batch(cnext, bufidx, 2);
        run_sub(sp, 3); issue_batch(cnext, bufidx, 3);
        run_sub(sp, 4); issue_batch(cnext, bufidx, 4);
        cp_commit();

        // ---------- sample at step c*100+99 ----------
        float x = DT * z;                       // i = DT*z
        if ((__float_as_uint(x) & 0x7f800000u) == 0x7f800000u) x = 0.0f; // nan/inf -> 0
        x = fmaxf(x, 1e-5f);
        if (x > cur_max) { cur_max = x; cur_arg = c; }
        const float lg = logf(x);
        if (c > 0) {
            const float d = lg - prev_lg;
            sumd  += d;
            sumd2 += d * d;
        }
        prev_lg = lg;
    }

    // drain remaining groups before exit (clamped refills of the last iterations)
    cp_wait<0>();

    // ---------- features ----------
    const float max_at = ((float)cur_arg + u[b]) / 49.0f;
    const float mean   = sumd * (1.0f / 48.0f);
    float var = sumd2 * (1.0f / 48.0f) - mean * mean;   // ddof=0
    var = fmaxf(var, 0.0f);

    out[b * 3 + 0] = cur_max;
    out[b * 3 + 1] = max_at;
    out[b * 3 + 2] = sqrtf(var);
}

extern "C" void kernel_launch(void* const* d_in, const int* in_sizes, int n_in,
                              void* d_out, int out_size)
{
    const float* cond = (const float*)d_in[0];   // (8192, 4)
    const float* dW   = (const float*)d_in[1];   // (5000, 8192)
    const float* u    = (const float*)d_in[2];   // (8192,)
    float* out        = (float*)d_out;           // (8192, 3)

    sir_sde_kernel<<<BSZ / THREADS, THREADS>>>(cond, dW, u, out);
}

// round 17
// speedup vs baseline: 1.2228x; 1.0003x over previous
#include <cuda_runtime.h>
#include <cuda_bf16.h>
#include <cstdint>

// SIR SDE: 8192 trajectories x 4900 steps, sampled every 100 steps (49 samples),
// features: max, (argmax+u)/49, std(diff(log x)).
//
// R17 = R16 (101.2us: CH=100, NBUF=3/AHEAD=2, 20-step sub-bursts, refills spread 5x5,
// uniform clamped refill -> invariant pending count, sample at chunk end) + ONE delta:
// abs folded into the sqrt asm block (abs.f32 adjacent to sqrt.approx.f32) so ptxas
// emits MUFU.SQRT with the |input| modifier, deleting the 4-cyc FABS link from the
// serial r0 chain (FFMA -> [FABS] -> MUFU). R10 tried this on the fragile shallow
// pipeline and the schedule perturbation collapsed the prefetch (HBM 826 GB/s);
// the R16 skeleton is robust to schedule jitter, isolating the abs-fold effect.

#define BSZ    8192
#define CH     100           // steps per chunk = sample period
#define HS     20            // sub-burst steps (proven unit)
#define NCHUNK 49
#define NBUF   3             // smem buffers per warp
#define AHEAD  2             // chunks in flight
#define WPB    2             // warps per block
#define THREADS (WPB * 32)

__device__ __forceinline__ void cp_async16(uint32_t saddr, const void* gptr) {
    asm volatile("cp.async.ca.shared.global [%0], [%1], 16;" :: "r"(saddr), "l"(gptr));
}
__device__ __forceinline__ void cp_commit() {
    asm volatile("cp.async.commit_group;");
}
template <int N>
__device__ __forceinline__ void cp_wait() {
    asm volatile("cp.async.wait_group %0;" :: "n"(N));
}
// sqrt(|x|) with abs adjacent to sqrt in one PTX block -> ptxas folds the abs into the
// MUFU input modifier (MUFU.SQRT Rd, |Rs|) instead of a separate 4-cyc FABS chain link.
__device__ __forceinline__ float sqrt_abs_approx(float x) {
    float r;
    asm("{ .reg .f32 ta; abs.f32 ta, %1; sqrt.approx.f32 %0, ta; }"
        : "=f"(r) : "f"(x));
    return r;
}

__global__ __launch_bounds__(THREADS, 1)
void sir_sde_kernel(const float* __restrict__ cond,
                    const float* __restrict__ dW,
                    const float* __restrict__ u,
                    float* __restrict__ out)
{
    __shared__ float sdw[WPB][NBUF * CH * 32];   // per-warp: 3 bufs x 100 steps x 32 lanes

    const int lane = threadIdx.x & 31;
    const int w    = threadIdx.x >> 5;
    const int b0   = blockIdx.x * THREADS + w * 32;   // first trajectory of this warp
    const int b    = b0 + lane;

    // ---------- per-trajectory parameters ----------
    const float inf_rate = cond[b * 4 + 0];
    const float rec      = cond[b * 4 + 1];
    const float mr       = cond[b * 4 + 2];
    const float vol      = cond[b * 4 + 3];

    const float DT      = 0.01f;
    const float r0_init = __fdiv_rn(inf_rate, rec);
    const float sdt     = sqrtf(DT);
    const float dtmr    = DT * mr;
    const float om      = 1.0f - dtmr;        // r0' = om*r0 + c1 + sqrt(|r0|)*c2
    const float c1      = dtmr * r0_init;
    const float kvol    = vol * sdt;
    const float ndtrec  = -DT * rec;          // q' = q + ndtrec*ni
    const float omr     = 1.0f + ndtrec;      // z' = omr*z + ni   (z = i/DT)

    // ---------- state (s -> q = rec*s, i -> z = i/DT) ----------
    float q  = rec * 0.99f;
    float z  = 1.0f;                          // i0 = 0.01 = DT*1
    float r0 = r0_init;

    // ---------- feature accumulators ----------
    float cur_max = -3.402823466e38f;
    int   cur_arg = 0;
    float prev_lg = 0.0f;
    float sumd = 0.0f, sumd2 = 0.0f;

    // ---------- cp.async machinery (per warp, self-contained) ----------
    uint32_t smem_base;
    asm("{ .reg .u64 t; cvta.to.shared.u64 t, %1; cvt.u32.u64 %0, t; }"
        : "=r"(smem_base) : "l"(&sdw[w][0]));

    const char* gbase = (const char*)(dW + b0);

    // one refill batch: 5 cp.asyncs = 2560 B = rows [h*20, h*20+20) of chunk c
    auto issue_batch = [&](int c, int bufidx, int h) {
        const char* g = gbase + (size_t)c * CH * BSZ * 4;
        uint32_t sb = smem_base + bufidx * (CH * 128);
#pragma unroll
        for (int i = 0; i < 5; ++i) {
            int f   = (h * 5 + i) * 512 + lane * 16;   // flat byte offset in buffer
            int row = f >> 7;                          // /128
            int col = f & 127;
            cp_async16(sb + f, g + (size_t)row * BSZ * 4 + col);
        }
    };

    // one 20-step sub-burst: LDS 20 noise values, run 20 Euler-Maruyama steps
    float dwv[HS];
    auto run_sub = [&](const float* sp, int h) {
#pragma unroll
        for (int k = 0; k < HS; ++k) dwv[k] = sp[(h * HS + k) * 32];
#pragma unroll
        for (int k = 0; k < HS; ++k) {
            const float c2 = dwv[k] * kvol;     // off the critical chain
            const float ni = r0 * q;            // newly_infected (= r0*rec*s)
            const float sq = sqrt_abs_approx(r0);  // chain: MUFU with |.| folded
            const float t  = fmaf(r0, om, c1);
            r0 = fmaf(sq, c2, t);               // chain: + FFMA
            q  = fmaf(ni, ndtrec, q);
            z  = fmaf(omr, z, ni);              // i-update in one FFMA (z = i/DT)
        }
    };

    // prologue: chunks 0,1 fully in flight (one group each)
#pragma unroll
    for (int p = 0; p < AHEAD; ++p) {
#pragma unroll
        for (int h = 0; h < 5; ++h) issue_batch(p, p, h);
        cp_commit();
    }

    const float* sbuf = &sdw[w][0];

#pragma unroll 1
    for (int c = 0; c < NCHUNK; ++c) {
        // Invariant: exactly 2 groups pending here ({c, c+1}); wait<1> drains chunk c.
        cp_wait<AHEAD - 1>();
        __syncwarp();

        const float* sp = sbuf + (c % NBUF) * (CH * 32) + lane;

        // refill target: always issue one full group; chunk index clamped at the end
        // (clamped groups fill buffers never read again -> harmless, keeps the
        // pending-group invariant so no tail special case is needed).
        const int cnext  = (c + AHEAD < NCHUNK) ? (c + AHEAD) : (NCHUNK - 1);
        const int bufidx = (c + AHEAD) % NBUF;

        run_sub(sp, 0); issue_batch(cnext, bufidx, 0);
        run_sub(sp, 1); issue_batch(cnext, bufidx, 1);
        run_sub(sp, 2); issue_batch(cnext, bufidx, 2);
        run_sub(sp, 3); issue_batch(cnext, bufidx, 3);
        run_sub(sp, 4); issue_batch(cnext, bufidx, 4);
        cp_commit();

        // ---------- sample at step c*100+99 ----------
        float x = DT * z;                       // i = DT*z
        if ((__float_as_uint(x) & 0x7f800000u) == 0x7f800000u) x = 0.0f; // nan/inf -> 0
        x = fmaxf(x, 1e-5f);
        if (x > cur_max) { cur_max = x; cur_arg = c; }
        const float lg = logf(x);
        if (c > 0) {
            const float d = lg - prev_lg;
            sumd  += d;
            sumd2 += d * d;
        }
        prev_lg = lg;
    }

    // drain remaining groups before exit (clamped refills of the last iterations)
    cp_wait<0>();

    // ---------- features ----------
    const float max_at = ((float)cur_arg + u[b]) / 49.0f;
    const float mean   = sumd * (1.0f / 48.0f);
    float var = sumd2 * (1.0f / 48.0f) - mean * mean;   // ddof=0
    var = fmaxf(var, 0.0f);

    out[b * 3 + 0] = cur_max;
    out[b * 3 + 1] = max_at;
    out[b * 3 + 2] = sqrtf(var);
}

extern "C" void kernel_launch(void* const* d_in, const int* in_sizes, int n_in,
                              void* d_out, int out_size)
{
    const float* cond = (const float*)d_in[0];   // (8192, 4)
    const float* dW   = (const float*)d_in[1];   // (5000, 8192)
    const float* u    = (const float*)d_in[2];   // (8192,)
    float* out        = (float*)d_out;           // (8192, 3)

    sir_sde_kernel<<<BSZ / THREADS, THREADS>>>(cond, dW, u, out);
}